// round 4
// baseline (speedup 1.0000x reference)
#include <cuda_runtime.h>
#include <cuda_bf16.h>

// Problem: cummax along axis=2 of x[B=8, Tt=128, Ts=128, C=512] fp32.
// out[b,t,j,c] = max_{j'<=j} x[b,t,j',c]
//
// R3: back to float4 (R2 proved width > occupancy for this stream), plus:
//  - __ldcs/__stcs streaming hints (data touched exactly once; evict-first)
//  - unroll 16 (8 -> 16 in-flight LDG.128 per warp, deeper DRAM queue)

static __device__ __forceinline__ float4 f4max(float4 a, float4 b) {
    float4 r;
    r.x = fmaxf(a.x, b.x);
    r.y = fmaxf(a.y, b.y);
    r.z = fmaxf(a.z, b.z);
    r.w = fmaxf(a.w, b.w);
    return r;
}

// B*Tt = 1024 rows, each row is [Ts=128, C=512].
// C/4 = 128 float4 per j. Columns total = 1024 * 128 = 131072 threads.
__global__ void __launch_bounds__(256) cummax_kernel(
    const float4* __restrict__ in, float4* __restrict__ out)
{
    constexpr int TS = 128;
    constexpr int C4 = 128;               // 512 channels / 4
    const int col = blockIdx.x * blockDim.x + threadIdx.x;  // 0..131071
    const int bt  = col >> 7;             // which (b,t) row
    const int c4  = col & 127;            // which float4 within C

    const float4* __restrict__ p = in  + (size_t)bt * TS * C4 + c4;
    float4* __restrict__       q = out + (size_t)bt * TS * C4 + c4;

    float4 m = __ldcs(p);
    __stcs(q, m);

    // Deep unroll: 16 independent LDG.128 batched ahead of the serial max
    // chain -> 16 outstanding loads per thread (M_max ~55, plenty of room).
    #pragma unroll 16
    for (int j = 1; j < TS; ++j) {
        float4 v = __ldcs(p + (size_t)j * C4);
        m = f4max(m, v);
        __stcs(q + (size_t)j * C4, m);
    }
}

extern "C" void kernel_launch(void* const* d_in, const int* in_sizes, int n_in,
                              void* d_out, int out_size)
{
    const float4* x = (const float4*)d_in[0];
    float4* y = (float4*)d_out;

    // total float4 columns = 8*128 * (512/4) = 131072
    const int threads = 256;
    const int total_cols = 8 * 128 * (512 / 4);
    const int blocks = total_cols / threads;  // 512
    cummax_kernel<<<blocks, threads>>>(x, y);
}

// round 5
// speedup vs baseline: 1.1670x; 1.1670x over previous
#include <cuda_runtime.h>
#include <cuda_bf16.h>
#include <math_constants.h>

// Problem: cummax along axis=2 of x[B=8, Tt=128, Ts=128, C=512] fp32.
// out[b,t,j,c] = max_{j'<=j} x[b,t,j',c]
//
// R4: revert ALL cache hints (two regressions traced to __ldcs/__stcs).
// Structural change vs R1: explicit batch-of-8 phases --
//   load 8 independent float4 -> serial prefix max -> store 8.
// Guarantees 8 front-batched LDG.128 in SASS (named regs force it) and
// groups reads/writes into bursts to cut DRAM R/W turnaround.

static __device__ __forceinline__ float4 f4max(float4 a, float4 b) {
    float4 r;
    r.x = fmaxf(a.x, b.x);
    r.y = fmaxf(a.y, b.y);
    r.z = fmaxf(a.z, b.z);
    r.w = fmaxf(a.w, b.w);
    return r;
}

// B*Tt = 1024 rows, each row is [Ts=128, C=512].
// C/4 = 128 float4 per j. Columns total = 1024 * 128 = 131072 threads.
__global__ void __launch_bounds__(256, 8) cummax_kernel(
    const float4* __restrict__ in, float4* __restrict__ out)
{
    constexpr int TS = 128;
    constexpr int C4 = 128;               // 512 channels / 4
    constexpr int JB = 8;                 // batch depth
    const int col = blockIdx.x * blockDim.x + threadIdx.x;  // 0..131071
    const int bt  = col >> 7;             // which (b,t) row
    const int c4  = col & 127;            // which float4 within C

    const float4* __restrict__ p = in  + (size_t)bt * TS * C4 + c4;
    float4* __restrict__       q = out + (size_t)bt * TS * C4 + c4;

    float4 m = make_float4(-CUDART_INF_F, -CUDART_INF_F,
                           -CUDART_INF_F, -CUDART_INF_F);

    #pragma unroll 1
    for (int jb = 0; jb < TS / JB; ++jb) {
        const size_t base = (size_t)(jb * JB) * C4;
        float4 v[JB];

        // Phase 1: 8 independent LDG.128 (no deps -> front-batched, MLP=8)
        #pragma unroll
        for (int u = 0; u < JB; ++u)
            v[u] = p[base + (size_t)u * C4];

        // Phase 2: serial prefix max with carry-in m (pure register work)
        #pragma unroll
        for (int u = 0; u < JB; ++u) {
            m = f4max(m, v[u]);
            v[u] = m;
        }

        // Phase 3: 8 STG.128 in a burst
        #pragma unroll
        for (int u = 0; u < JB; ++u)
            q[base + (size_t)u * C4] = v[u];
    }
}

extern "C" void kernel_launch(void* const* d_in, const int* in_sizes, int n_in,
                              void* d_out, int out_size)
{
    const float4* x = (const float4*)d_in[0];
    float4* y = (float4*)d_out;

    // total float4 columns = 8*128 * (512/4) = 131072
    const int threads = 256;
    const int total_cols = 8 * 128 * (512 / 4);
    const int blocks = total_cols / threads;  // 512
    cummax_kernel<<<blocks, threads>>>(x, y);
}